// round 2
// baseline (speedup 1.0000x reference)
#include <cuda_runtime.h>

// Nearest-neighbor 2x upsample, NHWC fp32, GB300 (sm_103a).
// In : (8, 128, 128, 256) fp32 = 128 MiB ; Out: (8, 256, 256, 256) = 512 MiB.
// Input-centric: each thread loads ONE 32-byte float8 (256-bit LDG, sm_100+)
// and stores it to the 4 replicated (2x2) output positions with 256-bit STG.
// Input read exactly once -> 640 MiB total DRAM traffic (the floor).
//
// Fixed shapes: B=8, H=W=128, C=256, factor=2.
// Work in float8 (32B) units: C8 = 256/8 = 32 chunks per pixel.
// Total float8 elements = 8*128*128*32 = 4,194,304.

__global__ __launch_bounds__(256) void upsample2x_v8_kernel(
    const float* __restrict__ in, float* __restrict__ out)
{
    const int idx = blockIdx.x * 256 + threadIdx.x;   // float8 index, 0..4194303

    // Decompose: ((b*128 + h)*128 + w)*32 + c8
    const int c8 = idx & 31;
    const int w  = (idx >> 5) & 127;
    const int h  = (idx >> 12) & 127;
    const int b  = idx >> 19;

    // 256-bit load (non-coherent: input is read exactly once)
    const float* src = in + ((long long)idx << 3);
    float v0, v1, v2, v3, v4, v5, v6, v7;
    asm volatile(
        "ld.global.nc.v8.f32 {%0,%1,%2,%3,%4,%5,%6,%7}, [%8];"
        : "=f"(v0), "=f"(v1), "=f"(v2), "=f"(v3),
          "=f"(v4), "=f"(v5), "=f"(v6), "=f"(v7)
        : "l"(src));

    // Output float8 index: ((b*256 + 2h+dh)*256 + 2w+dw)*32 + c8
    //   b stride  : 256*256*32 = 1<<21 (float8 units)
    //   2h stride : 2*256*32   = h<<14   (dh adds 1<<13)
    //   2w stride : 2*32       = w<<6    (dw adds 32)
    const int o8 = (b << 21) + (h << 14) + (w << 6) + c8;

    float* d00 = out + ((long long)o8 << 3);                       // (2h,   2w)
    float* d01 = d00 + 256;                                        // (2h,   2w+1)   +32 f8
    float* d10 = d00 + 65536;                                      // (2h+1, 2w)     +(1<<13) f8
    float* d11 = d10 + 256;                                        // (2h+1, 2w+1)

    asm volatile("st.global.v8.f32 [%0], {%1,%2,%3,%4,%5,%6,%7,%8};"
        :: "l"(d00), "f"(v0), "f"(v1), "f"(v2), "f"(v3),
                     "f"(v4), "f"(v5), "f"(v6), "f"(v7) : "memory");
    asm volatile("st.global.v8.f32 [%0], {%1,%2,%3,%4,%5,%6,%7,%8};"
        :: "l"(d01), "f"(v0), "f"(v1), "f"(v2), "f"(v3),
                     "f"(v4), "f"(v5), "f"(v6), "f"(v7) : "memory");
    asm volatile("st.global.v8.f32 [%0], {%1,%2,%3,%4,%5,%6,%7,%8};"
        :: "l"(d10), "f"(v0), "f"(v1), "f"(v2), "f"(v3),
                     "f"(v4), "f"(v5), "f"(v6), "f"(v7) : "memory");
    asm volatile("st.global.v8.f32 [%0], {%1,%2,%3,%4,%5,%6,%7,%8};"
        :: "l"(d11), "f"(v0), "f"(v1), "f"(v2), "f"(v3),
                     "f"(v4), "f"(v5), "f"(v6), "f"(v7) : "memory");
}

extern "C" void kernel_launch(void* const* d_in, const int* in_sizes, int n_in,
                              void* d_out, int out_size)
{
    const float* in  = (const float*)d_in[0];
    float*       out = (float*)d_out;

    const int n8 = 8 * 128 * 128 * 32;     // 4,194,304 float8 elements
    const int threads = 256;
    const int blocks  = n8 / threads;      // 16384

    upsample2x_v8_kernel<<<blocks, threads>>>(in, out);
}

// round 3
// speedup vs baseline: 1.0144x; 1.0144x over previous
#include <cuda_runtime.h>

// Nearest-neighbor 2x upsample, NHWC fp32, GB300 (sm_103a).
// In : (8, 128, 128, 256) fp32 = 128 MiB ; Out: (8, 256, 256, 256) = 512 MiB.
// Input-centric, float4 granularity (R2 showed 256-bit access is not better).
// Each thread handles TWO input float4 chunks with both loads issued up front
// (MLP=2 per thread, smoother DRAM read stream), then 8 stores.
// Streaming cache hints (__ldcs/__stcs): no L2 residency for either stream,
// since nothing is ever reused -> cleaner writeback pipelining.
//
// Fixed shapes: B=8, H=W=128, C=256, factor=2. C4 = 64 float4/pixel.
// Total float4 elements = 8*128*128*64 = 8,388,608.

__device__ __forceinline__ int out_base(int idx)
{
    // idx = ((b*128 + h)*128 + w)*64 + c4
    const int c4 = idx & 63;
    const int w  = (idx >> 6) & 127;
    const int h  = (idx >> 13) & 127;
    const int b  = idx >> 20;
    // out float4 index of (2h, 2w): b<<22 | h<<15 | w<<7 | c4
    return (b << 22) + (h << 15) + (w << 7) + c4;
}

__global__ __launch_bounds__(256) void upsample2x_k2(
    const float4* __restrict__ in, float4* __restrict__ out)
{
    const int base = blockIdx.x * 512 + threadIdx.x;
    const int i0 = base;         // first chunk
    const int i1 = base + 256;   // second chunk (block-contiguous)

    // Front-batched independent streaming loads (MLP = 2)
    const float4 a = __ldcs(in + i0);
    const float4 b = __ldcs(in + i1);

    const int o0 = out_base(i0);
    const int o1 = out_base(i1);

    // (2h,2w) ; (2h,2w+1)=+64 ; (2h+1,2w)=+1<<14 ; (2h+1,2w+1)
    __stcs(out + o0,                 a);
    __stcs(out + o0 + 64,            a);
    __stcs(out + o0 + (1 << 14),      a);
    __stcs(out + o0 + (1 << 14) + 64, a);

    __stcs(out + o1,                 b);
    __stcs(out + o1 + 64,            b);
    __stcs(out + o1 + (1 << 14),      b);
    __stcs(out + o1 + (1 << 14) + 64, b);
}

extern "C" void kernel_launch(void* const* d_in, const int* in_sizes, int n_in,
                              void* d_out, int out_size)
{
    const float4* in  = (const float4*)d_in[0];
    float4*       out = (float4*)d_out;

    const int n4 = 8 * 128 * 128 * 64;   // 8,388,608 float4
    const int threads = 256;
    const int blocks  = n4 / (threads * 2);  // 16384 (2 float4 per thread)

    upsample2x_k2<<<blocks, threads>>>(in, out);
}